// round 11
// baseline (speedup 1.0000x reference)
#include <cuda_runtime.h>
#include <cuda_bf16.h>
#include <cstdint>

// ---------------------------------------------------------------------------
// Problem constants:  num_model=2, b=32, L=512, s=26, q=512
// Output: posterior (2,32,512,512) float32  followed by loglik (2,32) float32
// ---------------------------------------------------------------------------
#define NM 2
#define NB 32
#define LT 512
#define QQ 512
#define SS 26
#define POST_N (NM*NB*LT*QQ)   // 16777216

#define RANKS 8        // CTAs per cluster
#define CCH 8          // chains per team
#define EBS 516        // ebuf per-chain stride in floats (padded: conflict-free)
#define EBUF_F (CCH*EBS)   // 4128 floats per buffer
#define SYS 68         // sY row stride in floats

// smem float offsets (dynamic smem, one block)
#define OFF_A     0        // A slice: 512*64 = 32768 floats (128KB)
#define OFF_EB    32768    // e buffers: 2 * 4128 = 8256 floats
#define OFF_SY    41024    // partials: 64 * 68 = 4352 floats
#define OFF_WRED  45376    // 16 floats
#define OFF_MLS   45392    // 8 floats (local chain maxes)
#define OFF_MR    45400    // 2 * 64 floats (per-rank maxes, double buffered)
#define SMEM_FLOATS 45528
#define SMEM_BYTES (SMEM_FLOATS*4)   // 182112 bytes

// ---------------------------------------------------------------------------
// Device scratch (static __device__ arrays: allocation-free at runtime)
// ---------------------------------------------------------------------------
__device__ float gA    [NM * QQ * QQ];       // softmax(transition_logits)
__device__ float gAT   [NM * QQ * QQ];       // transpose of gA
__device__ float gBT   [NM * SS * QQ];       // softmax(emission) transposed [m][s][q]
__device__ float gLinit[NM * QQ];            // log_softmax(init_logits)
__device__ float gLogE [NM * NB * LT * QQ];  // log(em + eps)
__device__ float gBeta [NM * NB * LT * QQ];  // betas
__device__ float gLoglik[NM * NB];
__device__ float gLLsum [8 * RANKS * CCH];   // fwd per-rank partial sums
__device__ float gLLmaxR[8 * RANKS * CCH];   // fwd per-rank local maxes

// ---------------------------------------------------------------------------
// PTX helpers
// ---------------------------------------------------------------------------
__device__ __forceinline__ uint32_t smem_u32(const void* p) {
    uint32_t a;
    asm("{ .reg .u64 t; cvta.to.shared.u64 t, %1; cvt.u32.u64 %0, t; }"
        : "=r"(a) : "l"(p));
    return a;
}
__device__ __forceinline__ uint32_t ctarank() {
    uint32_t r; asm("mov.u32 %0, %%cluster_ctarank;" : "=r"(r)); return r;
}
__device__ __forceinline__ void cluster_sync_all() {
    asm volatile("barrier.cluster.arrive.aligned;" ::: "memory");
    asm volatile("barrier.cluster.wait.aligned;" ::: "memory");
}
__device__ __forceinline__ void st_cluster_f32(uint32_t laddr, uint32_t peer, float v) {
    uint32_t ra;
    asm volatile("mapa.shared::cluster.u32 %0, %1, %2;" : "=r"(ra) : "r"(laddr), "r"(peer));
    asm volatile("st.shared::cluster.u32 [%0], %1;" :: "r"(ra), "r"(__float_as_uint(v)) : "memory");
}

#define FMA4(acc, s, v) { acc.x = fmaf((s),(v).x,acc.x); acc.y = fmaf((s),(v).y,acc.y); \
                          acc.z = fmaf((s),(v).z,acc.z); acc.w = fmaf((s),(v).w,acc.w); }

// ---------------------------------------------------------------------------
// Prep 1: transition softmax -> gA (prob space) and gAT (transpose)
// ---------------------------------------------------------------------------
__global__ __launch_bounds__(256) void prep_trans_kernel(const float* __restrict__ tl) {
    __shared__ float red[256];
    int row = blockIdx.x;                // m*QQ + k
    int m = row >> 9, k = row & (QQ - 1);
    int tid = threadIdx.x;
    float x0 = tl[row * QQ + tid];
    float x1 = tl[row * QQ + tid + 256];
    red[tid] = fmaxf(x0, x1);
    __syncthreads();
    for (int s = 128; s; s >>= 1) { if (tid < s) red[tid] = fmaxf(red[tid], red[tid + s]); __syncthreads(); }
    float M = red[0];
    __syncthreads();
    float e0 = __expf(x0 - M), e1 = __expf(x1 - M);
    red[tid] = e0 + e1;
    __syncthreads();
    for (int s = 128; s; s >>= 1) { if (tid < s) red[tid] += red[tid + s]; __syncthreads(); }
    float inv = 1.f / red[0];
    float p0 = e0 * inv, p1 = e1 * inv;
    gA[row * QQ + tid]       = p0;
    gA[row * QQ + tid + 256] = p1;
    size_t base = (size_t)m * QQ * QQ;
    gAT[base + (size_t)tid * QQ + k]         = p0;
    gAT[base + (size_t)(tid + 256) * QQ + k] = p1;
}

// ---------------------------------------------------------------------------
// Prep 2: init log_softmax -> gLinit
// ---------------------------------------------------------------------------
__global__ __launch_bounds__(256) void prep_init_kernel(const float* __restrict__ il) {
    __shared__ float red[256];
    int row = blockIdx.x;
    int tid = threadIdx.x;
    float x0 = il[row * QQ + tid];
    float x1 = il[row * QQ + tid + 256];
    red[tid] = fmaxf(x0, x1);
    __syncthreads();
    for (int s = 128; s; s >>= 1) { if (tid < s) red[tid] = fmaxf(red[tid], red[tid + s]); __syncthreads(); }
    float M = red[0];
    __syncthreads();
    float e0 = __expf(x0 - M), e1 = __expf(x1 - M);
    red[tid] = e0 + e1;
    __syncthreads();
    for (int s = 128; s; s >>= 1) { if (tid < s) red[tid] += red[tid + s]; __syncthreads(); }
    float ls = __logf(red[0]);
    gLinit[row * QQ + tid]       = x0 - M - ls;
    gLinit[row * QQ + tid + 256] = x1 - M - ls;
}

// ---------------------------------------------------------------------------
// Prep 3: emission softmax -> gBT[m][s][q]
// ---------------------------------------------------------------------------
__global__ __launch_bounds__(256) void prep_emis_kernel(const float* __restrict__ el) {
    const unsigned full = 0xffffffffu;
    int w = threadIdx.x >> 5, l = threadIdx.x & 31;
    int row = blockIdx.x * 8 + w;        // m*QQ + q
    int m = row >> 9, q = row & (QQ - 1);
    float v = (l < SS) ? el[row * SS + l] : -3.4e38f;
    float M = v;
    #pragma unroll
    for (int o = 16; o; o >>= 1) M = fmaxf(M, __shfl_xor_sync(full, M, o));
    float e = (l < SS) ? __expf(v - M) : 0.f;
    float s = e;
    #pragma unroll
    for (int o = 16; o; o >>= 1) s += __shfl_xor_sync(full, s, o);
    if (l < SS) gBT[(size_t)m * SS * QQ + (size_t)l * QQ + q] = e / s;
}

// ---------------------------------------------------------------------------
// Prep 4: logE[m,b,l,q] = log(sum_s inputs[m,b,l,s] * B[m,q,s] + eps)
// ---------------------------------------------------------------------------
__global__ __launch_bounds__(512) void prep_logE_kernel(const float* __restrict__ inp) {
    __shared__ float sIn[SS];
    int bx = blockIdx.x;
    int lt = bx & 63;
    int mb = bx >> 6;
    int m  = mb >> 5;
    int q  = threadIdx.x;
    float breg[SS];
    const float* bt = gBT + (size_t)m * SS * QQ;
    #pragma unroll
    for (int s = 0; s < SS; s++) breg[s] = bt[s * QQ + q];
    const float* ip = inp + ((size_t)mb * LT + (size_t)lt * 8) * SS;
    float* op = gLogE + ((size_t)mb * LT + (size_t)lt * 8) * QQ;
    for (int l = 0; l < 8; l++) {
        __syncthreads();
        if (q < SS) sIn[q] = ip[l * SS + q];
        __syncthreads();
        float em = 0.f;
        #pragma unroll
        for (int s = 0; s < SS; s++) em += breg[s] * sIn[s];
        op[l * QQ + q] = __logf(em + 1e-16f);
    }
}

// ---------------------------------------------------------------------------
// Scan tail: local per-chain max (rank-local shift), broadcast e + local max
// to all peers into buffer `buf`.  One cluster sync.  Returns this thread's e.
// ---------------------------------------------------------------------------
__device__ __forceinline__ float scan_tail(float g, int buf, int tid, int c, int eoff,
                                           uint32_t myrank, float* eb, float* wred,
                                           float* MlS, float* Mr) {
    const unsigned full = 0xffffffffu;
    float wm = g;
    #pragma unroll
    for (int o = 16; o; o >>= 1) wm = fmaxf(wm, __shfl_xor_sync(full, wm, o));
    if ((tid & 31) == 0) wred[tid >> 5] = wm;
    __syncthreads();
    if (tid < 8) {
        float lm = fmaxf(wred[2 * tid], wred[2 * tid + 1]);
        MlS[tid] = lm;
        float* dst = Mr + buf * 64 + (int)myrank * 8 + tid;
        *dst = lm;
        uint32_t la = smem_u32(dst);
        #pragma unroll
        for (int p = 0; p < RANKS; p++)
            if ((uint32_t)p != myrank) st_cluster_f32(la, (uint32_t)p, lm);
    }
    __syncthreads();
    float e = __expf(g - MlS[c]);
    float* d2 = eb + buf * EBUF_F + eoff;
    *d2 = e;
    uint32_t la2 = smem_u32(d2);
    #pragma unroll
    for (int p = 0; p < RANKS; p++)
        if ((uint32_t)p != myrank) st_cluster_f32(la2, (uint32_t)p, e);
    cluster_sync_all();
    return e;
}

// ---------------------------------------------------------------------------
// Main scan: 16 clusters of 8 CTAs (2 models x 2 dirs x 4 chain-groups).
// Each CTA: resident 512x64 A-slice in SMEM, computes its 64 output columns
// for 8 chains; e-state broadcast over DSMEM each step, 1 cluster sync/step.
// ---------------------------------------------------------------------------
__global__ void __launch_bounds__(512, 1) __cluster_dims__(RANKS, 1, 1)
hmm_scan_cluster(float* __restrict__ out) {
    extern __shared__ float sm[];
    float* sA   = sm + OFF_A;
    float* eb   = sm + OFF_EB;
    float* sY   = sm + OFF_SY;
    float* wred = sm + OFF_WRED;
    float* MlS  = sm + OFF_MLS;
    float* Mr   = sm + OFF_MR;

    int tid = threadIdx.x;
    uint32_t r = ctarank();
    int cid = blockIdx.x >> 3;
    int m   = cid >> 3;
    int dir = (cid >> 2) & 1;
    int grp = cid & 3;

    // load resident A slice: columns [r*64, r*64+64) of gA/gAT[m]
    const float* Asrc = (dir == 0 ? gA : gAT) + (size_t)m * QQ * QQ + (size_t)r * 64;
    for (int idx = tid; idx < QQ * 16; idx += 512) {
        int k = idx >> 4, c4 = idx & 15;
        ((float4*)sA)[k * 16 + c4] = ((const float4*)(Asrc + (size_t)k * QQ))[c4];
    }

    // output-phase mapping: thread -> (chain c, column col)
    int c = tid >> 6, col = tid & 63;
    // matvec-phase mapping: thread -> (k-slice kp, colgroup cg, chainpair cp)
    int cp = tid & 3, cg = (tid >> 2) & 15, kp = tid >> 6;

    int b  = grp * 8 + c;
    const float* le = gLogE + (size_t)(m * NB + b) * LT * QQ;
    float* stp = (dir == 0 ? out : gBeta) + (size_t)(m * NB + b) * LT * QQ;
    int jg   = (int)r * 64 + col;          // global column owned by this thread
    int eoff = c * EBS + jg;               // slot in e-buffer

    const float4* sA4 = (const float4*)sA;
    float4* sY4 = (float4*)sY;

    __syncthreads();
    cluster_sync_all();    // all peers resident before first DSMEM write

    // ---- init state ----
    float g;
    if (dir == 0) {
        g = gLinit[m * QQ + jg] + le[jg];
        stp[jg] = g;
    } else {
        stp[(size_t)(LT - 1) * QQ + jg] = 0.f;
        g = le[(size_t)(LT - 1) * QQ + jg];
    }

    int buf = 0;
    float e = scan_tail(g, buf, tid, c, eoff, r, eb, wred, MlS, Mr);

    // ---- 511 recurrence steps ----
    for (int i = 1; i < LT; i++) {
        int t = dir ? (LT - 1 - i) : i;

        // matvec: partial over k-slice [kp*64, kp*64+64), 4 cols, 2 chains
        const float* ecur = eb + buf * EBUF_F;
        const float4* e0p = (const float4*)(ecur + (2 * cp) * EBS) + kp * 16;
        const float4* e1p = (const float4*)(ecur + (2 * cp + 1) * EBS) + kp * 16;
        const float4* pA  = sA4 + kp * 64 * 16 + cg;
        float4 acc0 = make_float4(0.f, 0.f, 0.f, 0.f);
        float4 acc1 = make_float4(0.f, 0.f, 0.f, 0.f);
        #pragma unroll
        for (int k4 = 0; k4 < 16; k4++) {
            float4 e0 = e0p[k4], e1 = e1p[k4];
            float4 r0 = pA[0], r1 = pA[16], r2 = pA[32], r3 = pA[48];
            FMA4(acc0, e0.x, r0); FMA4(acc0, e0.y, r1); FMA4(acc0, e0.z, r2); FMA4(acc0, e0.w, r3);
            FMA4(acc1, e1.x, r0); FMA4(acc1, e1.y, r1); FMA4(acc1, e1.z, r2); FMA4(acc1, e1.w, r3);
            pA += 64;
        }
        sY4[(kp * 8 + 2 * cp) * 17 + cg]     = acc0;
        sY4[(kp * 8 + 2 * cp + 1) * 17 + cg] = acc1;
        __syncthreads();

        // weighted cross-rank reduce: k-slice kp == source rank kp, so
        // rescale each partial from that rank's local max to the global max.
        const float* mr = Mr + buf * 64;
        float Mv[8];
        #pragma unroll
        for (int rr = 0; rr < 8; rr++) Mv[rr] = mr[rr * 8 + c];
        float Mgl = Mv[0];
        #pragma unroll
        for (int rr = 1; rr < 8; rr++) Mgl = fmaxf(Mgl, Mv[rr]);
        float y = 0.f;
        #pragma unroll
        for (int rr = 0; rr < 8; rr++)
            y += __expf(Mv[rr] - Mgl) * sY[(rr * 8 + c) * SYS + col];

        float lE = le[(size_t)t * QQ + jg];
        float v, gn;
        if (dir == 0) { v = Mgl + __logf(y) + lE; gn = v; }
        else          { v = Mgl + __logf(y);      gn = v + lE; }
        stp[(size_t)t * QQ + jg] = v;
        g = gn;

        buf ^= 1;
        e = scan_tail(g, buf, tid, c, eoff, r, eb, wred, MlS, Mr);
    }

    // ---- forward teams: per-rank loglik partials (scale = final local max) ----
    if (dir == 0) {
        const unsigned full = 0xffffffffu;
        float ws = e;
        #pragma unroll
        for (int o = 16; o; o >>= 1) ws += __shfl_xor_sync(full, ws, o);
        if ((tid & 31) == 0) wred[tid >> 5] = ws;
        __syncthreads();
        if (tid < 8) {
            int team = m * 4 + grp;
            gLLsum [(team * 8 + (int)r) * 8 + tid] = wred[2 * tid] + wred[2 * tid + 1];
            gLLmaxR[(team * 8 + (int)r) * 8 + tid] = MlS[tid];
        }
    }
}

// ---------------------------------------------------------------------------
// Combine per-rank loglik partials: 64 threads, one per chain
// ---------------------------------------------------------------------------
__global__ void loglik_kernel() {
    int t = threadIdx.x;                // 0..63 = m*32 + b
    int mm = t >> 5, bb = t & 31;
    int team = mm * 4 + (bb >> 3), c = bb & 7;
    float Ms[8], Ss[8];
    float M = -3.4e38f;
    #pragma unroll
    for (int rr = 0; rr < 8; rr++) {
        Ms[rr] = gLLmaxR[(team * 8 + rr) * 8 + c];
        Ss[rr] = gLLsum [(team * 8 + rr) * 8 + c];
        M = fmaxf(M, Ms[rr]);
    }
    float s = 0.f;
    #pragma unroll
    for (int rr = 0; rr < 8; rr++) s += __expf(Ms[rr] - M) * Ss[rr];
    gLoglik[t] = M + __logf(s);
}

// ---------------------------------------------------------------------------
// Epilogue: posterior = alpha(in out) + beta - loglik; append loglik.
// ---------------------------------------------------------------------------
__global__ __launch_bounds__(256) void epilogue_kernel(float* __restrict__ out, int out_size) {
    size_t i4 = (size_t)blockIdx.x * 256 + threadIdx.x;
    float4 o  = ((const float4*)out)[i4];
    float4 bb = ((const float4*)gBeta)[i4];
    int chain = (int)(i4 >> 16);
    float ll = gLoglik[chain];
    o.x += bb.x - ll;
    o.y += bb.y - ll;
    o.z += bb.z - ll;
    o.w += bb.w - ll;
    ((float4*)out)[i4] = o;
    if (blockIdx.x == 0 && threadIdx.x < NM * NB && out_size >= POST_N + NM * NB)
        out[POST_N + threadIdx.x] = gLoglik[threadIdx.x];
}

// ---------------------------------------------------------------------------
// Launch
// ---------------------------------------------------------------------------
extern "C" void kernel_launch(void* const* d_in, const int* in_sizes, int n_in,
                              void* d_out, int out_size) {
    const float* inputs = (const float*)d_in[0];   // (2,32,512,26)
    const float* tl     = (const float*)d_in[1];   // (2,512,512)
    const float* el     = (const float*)d_in[2];   // (2,512,26)
    const float* il     = (const float*)d_in[3];   // (2,512)
    float* out = (float*)d_out;

    cudaFuncSetAttribute(hmm_scan_cluster,
                         cudaFuncAttributeMaxDynamicSharedMemorySize, SMEM_BYTES);

    prep_trans_kernel<<<NM * QQ, 256>>>(tl);
    prep_emis_kernel<<<128, 256>>>(el);
    prep_init_kernel<<<NM, 256>>>(il);
    prep_logE_kernel<<<NM * NB * (LT / 8), 512>>>(inputs);
    hmm_scan_cluster<<<16 * RANKS, 512, SMEM_BYTES>>>(out);
    loglik_kernel<<<1, 64>>>();
    epilogue_kernel<<<POST_N / 4 / 256, 256>>>(out, out_size);
}

// round 15
// speedup vs baseline: 1.0770x; 1.0770x over previous
#include <cuda_runtime.h>
#include <cuda_bf16.h>
#include <cstdint>

// Problem: num_model=2, b=32, L=512, s=26, q=512
// Output: posterior (2,32,512,512) f32, then loglik (2,32) f32
#define NM 2
#define NB 32
#define LT 512
#define QQ 512
#define SS 26
#define POST_N (NM*NB*LT*QQ)

#define RANKS 8
#define CCH 8
#define ERB (RANKS*CCH*68)     // 4352 floats per recv buffer (rank-major, pad 68)

// smem float offsets
#define OFF_A     0            // 512*64 = 32768 (128KB resident A slice)
#define OFF_EB    32768        // 2 * 4352
#define OFF_SY    41472        // 64 * 68 = 4352
#define OFF_WRED  45824        // 16
#define OFF_MLS   45840        // 8
#define OFF_MR    45848        // 2 * 64
#define SMEM_FLOATS 45976
#define SMEM_BYTES (SMEM_FLOATS*4)

typedef unsigned long long u64t;

__device__ float gA    [NM * QQ * QQ];
__device__ float gAT   [NM * QQ * QQ];
__device__ float gBT   [NM * SS * QQ];
__device__ float gLinit[NM * QQ];
__device__ float gLogE [NM * NB * LT * QQ];
__device__ float gBeta [NM * NB * LT * QQ];
__device__ float gLoglik[NM * NB];
__device__ float gLLsum [8 * RANKS * CCH];
__device__ float gLLmaxR[8 * RANKS * CCH];

__device__ __forceinline__ uint32_t smem_u32(const void* p) {
    uint32_t a;
    asm("{ .reg .u64 t; cvta.to.shared.u64 t, %1; cvt.u32.u64 %0, t; }" : "=r"(a) : "l"(p));
    return a;
}
__device__ __forceinline__ uint32_t ctarank() {
    uint32_t r; asm("mov.u32 %0, %%cluster_ctarank;" : "=r"(r)); return r;
}
__device__ __forceinline__ void cluster_sync_all() {
    asm volatile("barrier.cluster.arrive.aligned;" ::: "memory");
    asm volatile("barrier.cluster.wait.aligned;" ::: "memory");
}
__device__ __forceinline__ void st_cluster_f32(uint32_t laddr, uint32_t peer, float v) {
    uint32_t ra;
    asm volatile("mapa.shared::cluster.u32 %0, %1, %2;" : "=r"(ra) : "r"(laddr), "r"(peer));
    asm volatile("st.shared::cluster.u32 [%0], %1;" :: "r"(ra), "r"(__float_as_uint(v)) : "memory");
}
__device__ __forceinline__ void fma2(u64t& d, u64t a, u64t b) {
    asm("fma.rn.f32x2 %0, %1, %2, %0;" : "+l"(d) : "l"(a), "l"(b));
}
__device__ __forceinline__ u64t pack2(float x) {
    u64t r; asm("mov.b64 %0, {%1, %1};" : "=l"(r) : "r"(__float_as_uint(x)));
    return r;
}

// --------------------------- prep kernels (unchanged) ----------------------
__global__ __launch_bounds__(256) void prep_trans_kernel(const float* __restrict__ tl) {
    __shared__ float red[256];
    int row = blockIdx.x, m = row >> 9, k = row & (QQ - 1), tid = threadIdx.x;
    float x0 = tl[row * QQ + tid], x1 = tl[row * QQ + tid + 256];
    red[tid] = fmaxf(x0, x1); __syncthreads();
    for (int s = 128; s; s >>= 1) { if (tid < s) red[tid] = fmaxf(red[tid], red[tid + s]); __syncthreads(); }
    float M = red[0]; __syncthreads();
    float e0 = __expf(x0 - M), e1 = __expf(x1 - M);
    red[tid] = e0 + e1; __syncthreads();
    for (int s = 128; s; s >>= 1) { if (tid < s) red[tid] += red[tid + s]; __syncthreads(); }
    float inv = 1.f / red[0];
    float p0 = e0 * inv, p1 = e1 * inv;
    gA[row * QQ + tid] = p0; gA[row * QQ + tid + 256] = p1;
    size_t base = (size_t)m * QQ * QQ;
    gAT[base + (size_t)tid * QQ + k] = p0;
    gAT[base + (size_t)(tid + 256) * QQ + k] = p1;
}

__global__ __launch_bounds__(256) void prep_init_kernel(const float* __restrict__ il) {
    __shared__ float red[256];
    int row = blockIdx.x, tid = threadIdx.x;
    float x0 = il[row * QQ + tid], x1 = il[row * QQ + tid + 256];
    red[tid] = fmaxf(x0, x1); __syncthreads();
    for (int s = 128; s; s >>= 1) { if (tid < s) red[tid] = fmaxf(red[tid], red[tid + s]); __syncthreads(); }
    float M = red[0]; __syncthreads();
    float e0 = __expf(x0 - M), e1 = __expf(x1 - M);
    red[tid] = e0 + e1; __syncthreads();
    for (int s = 128; s; s >>= 1) { if (tid < s) red[tid] += red[tid + s]; __syncthreads(); }
    float ls = __logf(red[0]);
    gLinit[row * QQ + tid] = x0 - M - ls;
    gLinit[row * QQ + tid + 256] = x1 - M - ls;
}

__global__ __launch_bounds__(256) void prep_emis_kernel(const float* __restrict__ el) {
    const unsigned full = 0xffffffffu;
    int w = threadIdx.x >> 5, l = threadIdx.x & 31;
    int row = blockIdx.x * 8 + w, m = row >> 9, q = row & (QQ - 1);
    float v = (l < SS) ? el[row * SS + l] : -3.4e38f;
    float M = v;
    #pragma unroll
    for (int o = 16; o; o >>= 1) M = fmaxf(M, __shfl_xor_sync(full, M, o));
    float e = (l < SS) ? __expf(v - M) : 0.f;
    float s = e;
    #pragma unroll
    for (int o = 16; o; o >>= 1) s += __shfl_xor_sync(full, s, o);
    if (l < SS) gBT[(size_t)m * SS * QQ + (size_t)l * QQ + q] = e / s;
}

__global__ __launch_bounds__(512) void prep_logE_kernel(const float* __restrict__ inp) {
    __shared__ float sIn[SS];
    int bx = blockIdx.x, lt = bx & 63, mb = bx >> 6, m = mb >> 5, q = threadIdx.x;
    float breg[SS];
    const float* bt = gBT + (size_t)m * SS * QQ;
    #pragma unroll
    for (int s = 0; s < SS; s++) breg[s] = bt[s * QQ + q];
    const float* ip = inp + ((size_t)mb * LT + (size_t)lt * 8) * SS;
    float* op = gLogE + ((size_t)mb * LT + (size_t)lt * 8) * QQ;
    for (int l = 0; l < 8; l++) {
        __syncthreads();
        if (q < SS) sIn[q] = ip[l * SS + q];
        __syncthreads();
        float em = 0.f;
        #pragma unroll
        for (int s = 0; s < SS; s++) em += breg[s] * sIn[s];
        op[l * QQ + q] = __logf(em + 1e-16f);
    }
}

// ---------------------------------------------------------------------------
// scan_tail: rank-local max shift; broadcast maxes (scalar, 56 msgs) and
// e-vector (shfl-gathered, st.shared::cluster.v4 = 896 msgs) to all peers.
// ---------------------------------------------------------------------------
__device__ __forceinline__ float scan_tail(float g, int buf, int tid, int c, int col,
                                           uint32_t myrank, float* eb, float* wred,
                                           float* MlS, float* Mr) {
    const unsigned full = 0xffffffffu;
    int lane = tid & 31;
    float wm = g;
    #pragma unroll
    for (int o = 16; o; o >>= 1) wm = fmaxf(wm, __shfl_xor_sync(full, wm, o));
    if (lane == 0) wred[tid >> 5] = wm;
    __syncthreads();
    if (tid < 8) {
        float lm = fmaxf(wred[2 * tid], wred[2 * tid + 1]);
        MlS[tid] = lm;
        float* dst = Mr + buf * 64 + (int)myrank * 8 + tid;
        *dst = lm;
        uint32_t la = smem_u32(dst);
        #pragma unroll
        for (int p = 0; p < RANKS; p++)
            if ((uint32_t)p != myrank) st_cluster_f32(la, (uint32_t)p, lm);
    }
    __syncthreads();
    float e = __expf(g - MlS[c]);
    float* rb = eb + buf * ERB + (int)myrank * (CCH * 68);
    rb[c * 68 + col] = e;                         // self slot
    // gather 4 lane-values into pusher lanes 0..7
    float g0 = __shfl_sync(full, e, lane * 4);
    float g1 = __shfl_sync(full, e, lane * 4 + 1);
    float g2 = __shfl_sync(full, e, lane * 4 + 2);
    float g3 = __shfl_sync(full, e, lane * 4 + 3);
    if (lane < 8) {
        int h = (tid >> 5) & 1;                   // column half of this warp
        uint32_t la = smem_u32(rb + c * 68 + h * 32 + lane * 4);
        #pragma unroll
        for (int p = 0; p < RANKS; p++)
            if ((uint32_t)p != myrank) {
                uint32_t ra;
                asm volatile("mapa.shared::cluster.u32 %0, %1, %2;" : "=r"(ra) : "r"(la), "r"(p));
                asm volatile("st.shared::cluster.v4.b32 [%0], {%1,%2,%3,%4};"
                             :: "r"(ra), "r"(__float_as_uint(g0)), "r"(__float_as_uint(g1)),
                                "r"(__float_as_uint(g2)), "r"(__float_as_uint(g3)) : "memory");
            }
    }
    cluster_sync_all();
    return e;
}

// ---------------------------------------------------------------------------
// Main scan: 16 clusters x 8 CTAs; A slice resident in SMEM; f32x2 matvec.
// ---------------------------------------------------------------------------
__global__ void __launch_bounds__(512, 1) __cluster_dims__(RANKS, 1, 1)
hmm_scan_cluster(float* __restrict__ out) {
    extern __shared__ float sm[];
    float* sA   = sm + OFF_A;
    float* eb   = sm + OFF_EB;
    float* sY   = sm + OFF_SY;
    float* wred = sm + OFF_WRED;
    float* MlS  = sm + OFF_MLS;
    float* Mr   = sm + OFF_MR;

    int tid = threadIdx.x;
    uint32_t r = ctarank();
    int cid = blockIdx.x >> 3;
    int m = cid >> 3, dir = (cid >> 2) & 1, grp = cid & 3;

    const float* Asrc = (dir == 0 ? gA : gAT) + (size_t)m * QQ * QQ + (size_t)r * 64;
    for (int idx = tid; idx < QQ * 16; idx += 512) {
        int k = idx >> 4, c4 = idx & 15;
        ((float4*)sA)[idx] = ((const float4*)(Asrc + (size_t)k * QQ))[c4];
    }

    int c = tid >> 6, col = tid & 63;                 // output mapping
    int cp = tid & 3, cg = (tid >> 2) & 15, kp = tid >> 6;  // matvec mapping

    int b = grp * 8 + c;
    const float* le = gLogE + (size_t)(m * NB + b) * LT * QQ;
    float* stp = (dir == 0 ? out : gBeta) + (size_t)(m * NB + b) * LT * QQ;
    int jg = (int)r * 64 + col;

    const ulonglong2* sA2 = (const ulonglong2*)sA;

    __syncthreads();
    cluster_sync_all();

    float g;
    if (dir == 0) {
        g = gLinit[m * QQ + jg] + le[jg];
        stp[jg] = g;
    } else {
        stp[(size_t)(LT - 1) * QQ + jg] = 0.f;
        g = le[(size_t)(LT - 1) * QQ + jg];
    }

    int buf = 0;
    float e = scan_tail(g, buf, tid, c, col, r, eb, wred, MlS, Mr);

    for (int i = 1; i < LT; i++) {
        int t = dir ? (LT - 1 - i) : i;
        float lE = le[(size_t)t * QQ + jg];           // prefetch: hidden by matvec

        const float* ecur = eb + buf * ERB;
        const float4* e0p = (const float4*)(ecur + kp * (CCH * 68) + (2 * cp) * 68);
        const float4* e1p = (const float4*)(ecur + kp * (CCH * 68) + (2 * cp + 1) * 68);
        const ulonglong2* pA = sA2 + (kp * 64 * 16 + cg);
        u64t a00 = 0, a01 = 0, a10 = 0, a11 = 0;
        #pragma unroll
        for (int k4 = 0; k4 < 16; k4++) {
            float4 qa = e0p[k4], qb = e1p[k4];
            ulonglong2 r0 = pA[0], r1 = pA[16], r2 = pA[32], r3 = pA[48];
            u64t s;
            s = pack2(qa.x); fma2(a00, s, r0.x); fma2(a01, s, r0.y);
            s = pack2(qb.x); fma2(a10, s, r0.x); fma2(a11, s, r0.y);
            s = pack2(qa.y); fma2(a00, s, r1.x); fma2(a01, s, r1.y);
            s = pack2(qb.y); fma2(a10, s, r1.x); fma2(a11, s, r1.y);
            s = pack2(qa.z); fma2(a00, s, r2.x); fma2(a01, s, r2.y);
            s = pack2(qb.z); fma2(a10, s, r2.x); fma2(a11, s, r2.y);
            s = pack2(qa.w); fma2(a00, s, r3.x); fma2(a01, s, r3.y);
            s = pack2(qb.w); fma2(a10, s, r3.x); fma2(a11, s, r3.y);
            pA += 64;
        }
        {
            ulonglong2 t0; t0.x = a00; t0.y = a01;
            *((ulonglong2*)(sY + (kp * 8 + 2 * cp) * 68) + cg) = t0;
            ulonglong2 t1; t1.x = a10; t1.y = a11;
            *((ulonglong2*)(sY + (kp * 8 + 2 * cp + 1) * 68) + cg) = t1;
        }
        __syncthreads();

        // weighted cross-rank reduce (k-slice kp == source rank kp)
        const float* mr = Mr + buf * 64;
        float Mv[8];
        #pragma unroll
        for (int rr = 0; rr < 8; rr++) Mv[rr] = mr[rr * 8 + c];
        float Mgl = Mv[0];
        #pragma unroll
        for (int rr = 1; rr < 8; rr++) Mgl = fmaxf(Mgl, Mv[rr]);
        float y = 0.f;
        #pragma unroll
        for (int rr = 0; rr < 8; rr++)
            y += __expf(Mv[rr] - Mgl) * sY[(rr * 8 + c) * 68 + col];

        float v, gn;
        if (dir == 0) { v = Mgl + __logf(y) + lE; gn = v; }
        else          { v = Mgl + __logf(y);      gn = v + lE; }
        stp[(size_t)t * QQ + jg] = v;
        g = gn;

        buf ^= 1;
        e = scan_tail(g, buf, tid, c, col, r, eb, wred, MlS, Mr);
    }

    if (dir == 0) {
        const unsigned full = 0xffffffffu;
        float ws = e;
        #pragma unroll
        for (int o = 16; o; o >>= 1) ws += __shfl_xor_sync(full, ws, o);
        if ((tid & 31) == 0) wred[tid >> 5] = ws;
        __syncthreads();
        if (tid < 8) {
            int team = m * 4 + grp;
            gLLsum [(team * 8 + (int)r) * 8 + tid] = wred[2 * tid] + wred[2 * tid + 1];
            gLLmaxR[(team * 8 + (int)r) * 8 + tid] = MlS[tid];
        }
    }
}

__global__ void loglik_kernel() {
    int t = threadIdx.x;
    int mm = t >> 5, bb = t & 31;
    int team = mm * 4 + (bb >> 3), c = bb & 7;
    float Ms[8], Ss[8], M = -3.4e38f;
    #pragma unroll
    for (int rr = 0; rr < 8; rr++) {
        Ms[rr] = gLLmaxR[(team * 8 + rr) * 8 + c];
        Ss[rr] = gLLsum [(team * 8 + rr) * 8 + c];
        M = fmaxf(M, Ms[rr]);
    }
    float s = 0.f;
    #pragma unroll
    for (int rr = 0; rr < 8; rr++) s += __expf(Ms[rr] - M) * Ss[rr];
    gLoglik[t] = M + __logf(s);
}

__global__ __launch_bounds__(256) void epilogue_kernel(float* __restrict__ out, int out_size) {
    size_t i4 = (size_t)blockIdx.x * 256 + threadIdx.x;
    float4 o  = ((const float4*)out)[i4];
    float4 bb = ((const float4*)gBeta)[i4];
    float ll = gLoglik[(int)(i4 >> 16)];
    o.x += bb.x - ll; o.y += bb.y - ll; o.z += bb.z - ll; o.w += bb.w - ll;
    ((float4*)out)[i4] = o;
    if (blockIdx.x == 0 && threadIdx.x < NM * NB && out_size >= POST_N + NM * NB)
        out[POST_N + threadIdx.x] = gLoglik[threadIdx.x];
}

extern "C" void kernel_launch(void* const* d_in, const int* in_sizes, int n_in,
                              void* d_out, int out_size) {
    const float* inputs = (const float*)d_in[0];
    const float* tl     = (const float*)d_in[1];
    const float* el     = (const float*)d_in[2];
    const float* il     = (const float*)d_in[3];
    float* out = (float*)d_out;

    cudaFuncSetAttribute(hmm_scan_cluster,
                         cudaFuncAttributeMaxDynamicSharedMemorySize, SMEM_BYTES);

    prep_trans_kernel<<<NM * QQ, 256>>>(tl);
    prep_emis_kernel<<<128, 256>>>(el);
    prep_init_kernel<<<NM, 256>>>(il);
    prep_logE_kernel<<<NM * NB * (LT / 8), 512>>>(inputs);
    hmm_scan_cluster<<<16 * RANKS, 512, SMEM_BYTES>>>(out);
    loglik_kernel<<<1, 64>>>();
    epilogue_kernel<<<POST_N / 4 / 256, 256>>>(out, out_size);
}

// round 16
// speedup vs baseline: 1.2372x; 1.1488x over previous
#include <cuda_runtime.h>
#include <cuda_bf16.h>
#include <cstdint>

#define NM 2
#define NB 32
#define LT 512
#define QQ 512
#define SS 26
#define POST_N (NM*NB*LT*QQ)

#define RANKS 8
#define CCH 8
#define BLK 552                 // 8 chains * 68 (e, padded) + 8 maxes
#define TXB (BLK*4)             // 2208 bytes per copy
#define TXTOT (RANKS*TXB)       // expected bytes per phase
#define RBUF (RANKS*BLK)        // 4416 floats per recv buffer

// smem float offsets
#define OFF_A     0             // 512*64 = 32768 floats (128KB)
#define OFF_RECV  32768         // 2*4416 = 8832
#define OFF_STAGE 41600         // 2*552 = 1104
#define OFF_SY    42704         // 64*68 = 4352
#define OFF_WRED  47056         // 16
#define OFF_MLS   47072         // 8
#define OFF_MB    47080         // 2 u64 barriers (16B)
#define SMEM_FLOATS 47088
#define SMEM_BYTES (SMEM_FLOATS*4)   // 188352

typedef unsigned long long u64t;

__device__ float gA    [NM * QQ * QQ];
__device__ float gAT   [NM * QQ * QQ];
__device__ float gBT   [NM * SS * QQ];
__device__ float gLinit[NM * QQ];
__device__ float gLogE [NM * NB * LT * QQ];
__device__ float gBeta [NM * NB * LT * QQ];
__device__ float gLoglik[NM * NB];
__device__ float gLLsum [8 * RANKS * CCH];
__device__ float gLLmaxR[8 * RANKS * CCH];

__device__ __forceinline__ uint32_t smem_u32(const void* p) {
    uint32_t a;
    asm("{ .reg .u64 t; cvta.to.shared.u64 t, %1; cvt.u32.u64 %0, t; }" : "=r"(a) : "l"(p));
    return a;
}
__device__ __forceinline__ uint32_t ctarank() {
    uint32_t r; asm("mov.u32 %0, %%cluster_ctarank;" : "=r"(r)); return r;
}
__device__ __forceinline__ void cluster_sync_all() {
    asm volatile("barrier.cluster.arrive.aligned;" ::: "memory");
    asm volatile("barrier.cluster.wait.aligned;" ::: "memory");
}
__device__ __forceinline__ void mbar_wait(uint32_t mbar, uint32_t parity) {
    asm volatile(
        "{\n\t.reg .pred P;\n\t"
        "WL%=:\n\t"
        "mbarrier.try_wait.parity.acquire.cta.shared::cta.b64 P, [%0], %1, 0x989680;\n\t"
        "@P bra.uni WD%=;\n\t"
        "bra.uni WL%=;\n\t"
        "WD%=:\n\t}"
        :: "r"(mbar), "r"(parity) : "memory");
}
__device__ __forceinline__ void mbar_arm(uint32_t mbar, uint32_t tx) {
    asm volatile("mbarrier.arrive.expect_tx.shared.b64 _, [%0], %1;"
                 :: "r"(mbar), "r"(tx) : "memory");
}
__device__ __forceinline__ void fma2(u64t& d, u64t a, u64t b) {
    asm("fma.rn.f32x2 %0, %1, %2, %0;" : "+l"(d) : "l"(a), "l"(b));
}
__device__ __forceinline__ u64t pack2(float x) {
    u64t r; asm("mov.b64 %0, {%1, %1};" : "=l"(r) : "r"(__float_as_uint(x)));
    return r;
}

// --------------------------- prep kernels ----------------------------------
__global__ __launch_bounds__(256) void prep_trans_kernel(const float* __restrict__ tl) {
    __shared__ float red[256];
    int row = blockIdx.x, m = row >> 9, k = row & (QQ - 1), tid = threadIdx.x;
    float x0 = tl[row * QQ + tid], x1 = tl[row * QQ + tid + 256];
    red[tid] = fmaxf(x0, x1); __syncthreads();
    for (int s = 128; s; s >>= 1) { if (tid < s) red[tid] = fmaxf(red[tid], red[tid + s]); __syncthreads(); }
    float M = red[0]; __syncthreads();
    float e0 = __expf(x0 - M), e1 = __expf(x1 - M);
    red[tid] = e0 + e1; __syncthreads();
    for (int s = 128; s; s >>= 1) { if (tid < s) red[tid] += red[tid + s]; __syncthreads(); }
    float inv = 1.f / red[0];
    float p0 = e0 * inv, p1 = e1 * inv;
    gA[row * QQ + tid] = p0; gA[row * QQ + tid + 256] = p1;
    size_t base = (size_t)m * QQ * QQ;
    gAT[base + (size_t)tid * QQ + k] = p0;
    gAT[base + (size_t)(tid + 256) * QQ + k] = p1;
}

__global__ __launch_bounds__(256) void prep_init_kernel(const float* __restrict__ il) {
    __shared__ float red[256];
    int row = blockIdx.x, tid = threadIdx.x;
    float x0 = il[row * QQ + tid], x1 = il[row * QQ + tid + 256];
    red[tid] = fmaxf(x0, x1); __syncthreads();
    for (int s = 128; s; s >>= 1) { if (tid < s) red[tid] = fmaxf(red[tid], red[tid + s]); __syncthreads(); }
    float M = red[0]; __syncthreads();
    float e0 = __expf(x0 - M), e1 = __expf(x1 - M);
    red[tid] = e0 + e1; __syncthreads();
    for (int s = 128; s; s >>= 1) { if (tid < s) red[tid] += red[tid + s]; __syncthreads(); }
    float ls = __logf(red[0]);
    gLinit[row * QQ + tid] = x0 - M - ls;
    gLinit[row * QQ + tid + 256] = x1 - M - ls;
}

__global__ __launch_bounds__(256) void prep_emis_kernel(const float* __restrict__ el) {
    const unsigned full = 0xffffffffu;
    int w = threadIdx.x >> 5, l = threadIdx.x & 31;
    int row = blockIdx.x * 8 + w, m = row >> 9, q = row & (QQ - 1);
    float v = (l < SS) ? el[row * SS + l] : -3.4e38f;
    float M = v;
    #pragma unroll
    for (int o = 16; o; o >>= 1) M = fmaxf(M, __shfl_xor_sync(full, M, o));
    float e = (l < SS) ? __expf(v - M) : 0.f;
    float s = e;
    #pragma unroll
    for (int o = 16; o; o >>= 1) s += __shfl_xor_sync(full, s, o);
    if (l < SS) gBT[(size_t)m * SS * QQ + (size_t)l * QQ + q] = e / s;
}

__global__ __launch_bounds__(512) void prep_logE_kernel(const float* __restrict__ inp) {
    __shared__ float sIn[SS];
    int bx = blockIdx.x, lt = bx & 63, mb = bx >> 6, m = mb >> 5, q = threadIdx.x;
    float breg[SS];
    const float* bt = gBT + (size_t)m * SS * QQ;
    #pragma unroll
    for (int s = 0; s < SS; s++) breg[s] = bt[s * QQ + q];
    const float* ip = inp + ((size_t)mb * LT + (size_t)lt * 8) * SS;
    float* op = gLogE + ((size_t)mb * LT + (size_t)lt * 8) * QQ;
    for (int l = 0; l < 8; l++) {
        __syncthreads();
        if (q < SS) sIn[q] = ip[l * SS + q];
        __syncthreads();
        float em = 0.f;
        #pragma unroll
        for (int s = 0; s < SS; s++) em += breg[s] * sIn[s];
        op[l * QQ + q] = __logf(em + 1e-16f);
    }
}

// ---------------------------------------------------------------------------
// produce: rank-local max shift; write e + maxes into stage[sb]; bulk-copy
// the 2208B block to all 8 ranks' recv[sb], complete_tx on their FULL[sb].
// ---------------------------------------------------------------------------
__device__ __forceinline__ void produce(float g, int sb, int tid, int c, int col,
                                        uint32_t myrank, float* stage, float* recv,
                                        float* wred, float* MlS, uint32_t mb_base) {
    const unsigned full = 0xffffffffu;
    int lane = tid & 31;
    float* stg = stage + sb * BLK;
    float wm = g;
    #pragma unroll
    for (int o = 16; o; o >>= 1) wm = fmaxf(wm, __shfl_xor_sync(full, wm, o));
    if (lane == 0) wred[tid >> 5] = wm;
    __syncthreads();
    if (tid < 8) {
        float lm = fmaxf(wred[2 * tid], wred[2 * tid + 1]);
        MlS[tid] = lm;
        stg[544 + tid] = lm;
    }
    __syncthreads();
    stg[c * 68 + col] = __expf(g - MlS[c]);
    __syncthreads();
    if (tid < 8) {
        asm volatile("fence.proxy.async.shared::cta;" ::: "memory");
        uint32_t src  = smem_u32(stg);
        uint32_t dstl = smem_u32(recv + sb * RBUF + (int)myrank * BLK);
        uint32_t mbl  = mb_base + sb * 8;
        uint32_t peer = (uint32_t)tid;
        uint32_t dstr, mbr;
        asm("mapa.shared::cluster.u32 %0, %1, %2;" : "=r"(dstr) : "r"(dstl), "r"(peer));
        asm("mapa.shared::cluster.u32 %0, %1, %2;" : "=r"(mbr)  : "r"(mbl),  "r"(peer));
        asm volatile(
            "cp.async.bulk.shared::cluster.shared::cta.mbarrier::complete_tx::bytes "
            "[%0], [%1], %2, [%3];"
            :: "r"(dstr), "r"(src), "r"(TXB), "r"(mbr) : "memory");
    }
}

// ---------------------------------------------------------------------------
// Main scan: 16 clusters x 8 CTAs; A resident in SMEM; f32x2 matvec;
// async bulk-copy exchange, double-buffered mbarriers, no in-loop cluster sync.
// ---------------------------------------------------------------------------
__global__ void __launch_bounds__(512, 1) __cluster_dims__(RANKS, 1, 1)
hmm_scan_cluster(float* __restrict__ out) {
    extern __shared__ float sm[];
    float* sA    = sm + OFF_A;
    float* recv  = sm + OFF_RECV;
    float* stage = sm + OFF_STAGE;
    float* sY    = sm + OFF_SY;
    float* wred  = sm + OFF_WRED;
    float* MlS   = sm + OFF_MLS;
    uint32_t mb_base = smem_u32(sm + OFF_MB);

    int tid = threadIdx.x;
    uint32_t r = ctarank();
    int cid = blockIdx.x >> 3;
    int m = cid >> 3, dir = (cid >> 2) & 1, grp = cid & 3;

    const float* Asrc = (dir == 0 ? gA : gAT) + (size_t)m * QQ * QQ + (size_t)r * 64;
    for (int idx = tid; idx < QQ * 16; idx += 512) {
        int k = idx >> 4, c4 = idx & 15;
        ((float4*)sA)[idx] = ((const float4*)(Asrc + (size_t)k * QQ))[c4];
    }

    if (tid == 0) {
        asm volatile("mbarrier.init.shared.b64 [%0], 1;" :: "r"(mb_base));
        asm volatile("mbarrier.init.shared.b64 [%0], 1;" :: "r"(mb_base + 8));
        mbar_arm(mb_base, TXTOT);        // buf0 (first used step 2)
        mbar_arm(mb_base + 8, TXTOT);    // buf1 (first used step 1)
    }

    int c = tid >> 6, col = tid & 63;
    int cp = tid & 3, cg = (tid >> 2) & 15, kp = tid >> 6;

    int b = grp * 8 + c;
    const float* le = gLogE + (size_t)(m * NB + b) * LT * QQ;
    float* stp = (dir == 0 ? out : gBeta) + (size_t)(m * NB + b) * LT * QQ;
    int jg = (int)r * 64 + col;

    const ulonglong2* sA2 = (const ulonglong2*)sA;

    __syncthreads();
    cluster_sync_all();     // barriers armed cluster-wide before any copy

    float g;
    if (dir == 0) {
        g = gLinit[m * QQ + jg] + le[jg];
        stp[jg] = g;
    } else {
        stp[(size_t)(LT - 1) * QQ + jg] = 0.f;
        g = le[(size_t)(LT - 1) * QQ + jg];
    }
    produce(g, 1, tid, c, col, r, stage, recv, wred, MlS, mb_base);

    int par[2] = {0, 0};
    for (int i = 1; i < LT; i++) {
        int t = dir ? (LT - 1 - i) : i;
        int bu = i & 1;
        mbar_wait(mb_base + bu * 8, (uint32_t)par[bu]);
        par[bu] ^= 1;
        if (tid == 0) mbar_arm(mb_base + bu * 8, TXTOT);   // re-arm for step i+2

        float lE = le[(size_t)t * QQ + jg];                // hidden by matvec

        const float* rb = recv + bu * RBUF;
        const float4* e0p = (const float4*)(rb + kp * BLK + (2 * cp) * 68);
        const float4* e1p = (const float4*)(rb + kp * BLK + (2 * cp + 1) * 68);
        const ulonglong2* pA = sA2 + (kp * 64 * 16 + cg);
        u64t a00 = 0, a01 = 0, a10 = 0, a11 = 0;
        #pragma unroll
        for (int k4 = 0; k4 < 16; k4++) {
            float4 qa = e0p[k4], qb = e1p[k4];
            ulonglong2 r0 = pA[0], r1 = pA[16], r2 = pA[32], r3 = pA[48];
            u64t s;
            s = pack2(qa.x); fma2(a00, s, r0.x); fma2(a01, s, r0.y);
            s = pack2(qb.x); fma2(a10, s, r0.x); fma2(a11, s, r0.y);
            s = pack2(qa.y); fma2(a00, s, r1.x); fma2(a01, s, r1.y);
            s = pack2(qb.y); fma2(a10, s, r1.x); fma2(a11, s, r1.y);
            s = pack2(qa.z); fma2(a00, s, r2.x); fma2(a01, s, r2.y);
            s = pack2(qb.z); fma2(a10, s, r2.x); fma2(a11, s, r2.y);
            s = pack2(qa.w); fma2(a00, s, r3.x); fma2(a01, s, r3.y);
            s = pack2(qb.w); fma2(a10, s, r3.x); fma2(a11, s, r3.y);
            pA += 64;
        }
        {
            ulonglong2 t0; t0.x = a00; t0.y = a01;
            *((ulonglong2*)(sY + (kp * 8 + 2 * cp) * 68) + cg) = t0;
            ulonglong2 t1; t1.x = a10; t1.y = a11;
            *((ulonglong2*)(sY + (kp * 8 + 2 * cp + 1) * 68) + cg) = t1;
        }
        __syncthreads();

        // weighted cross-rank reduce (k-slice kp == source rank kp)
        float Mv[8];
        #pragma unroll
        for (int rr = 0; rr < 8; rr++) Mv[rr] = rb[rr * BLK + 544 + c];
        float Mgl = Mv[0];
        #pragma unroll
        for (int rr = 1; rr < 8; rr++) Mgl = fmaxf(Mgl, Mv[rr]);
        float y = 0.f;
        #pragma unroll
        for (int rr = 0; rr < 8; rr++)
            y += __expf(Mv[rr] - Mgl) * sY[(rr * 8 + c) * 68 + col];

        float v, gn;
        if (dir == 0) { v = Mgl + __logf(y) + lE; gn = v; }
        else          { v = Mgl + __logf(y);      gn = v + lE; }
        stp[(size_t)t * QQ + jg] = v;
        g = gn;

        if (i < LT - 1)
            produce(g, (i + 1) & 1, tid, c, col, r, stage, recv, wred, MlS, mb_base);
    }

    // ---- forward teams: final local max + per-rank loglik partial sums ----
    if (dir == 0) {
        const unsigned full = 0xffffffffu;
        int lane = tid & 31;
        float wm = g;
        #pragma unroll
        for (int o = 16; o; o >>= 1) wm = fmaxf(wm, __shfl_xor_sync(full, wm, o));
        if (lane == 0) wred[tid >> 5] = wm;
        __syncthreads();
        if (tid < 8) MlS[tid] = fmaxf(wred[2 * tid], wred[2 * tid + 1]);
        __syncthreads();
        float e = __expf(g - MlS[c]);
        float ws = e;
        #pragma unroll
        for (int o = 16; o; o >>= 1) ws += __shfl_xor_sync(full, ws, o);
        if (lane == 0) wred[tid >> 5] = ws;
        __syncthreads();
        if (tid < 8) {
            int team = m * 4 + grp;
            gLLsum [(team * 8 + (int)r) * 8 + tid] = wred[2 * tid] + wred[2 * tid + 1];
            gLLmaxR[(team * 8 + (int)r) * 8 + tid] = MlS[tid];
        }
    }
    cluster_sync_all();   // no CTA exits while peers' inbound copies pending
}

__global__ void loglik_kernel() {
    int t = threadIdx.x;
    int mm = t >> 5, bb = t & 31;
    int team = mm * 4 + (bb >> 3), c = bb & 7;
    float Ms[8], Ss[8], M = -3.4e38f;
    #pragma unroll
    for (int rr = 0; rr < 8; rr++) {
        Ms[rr] = gLLmaxR[(team * 8 + rr) * 8 + c];
        Ss[rr] = gLLsum [(team * 8 + rr) * 8 + c];
        M = fmaxf(M, Ms[rr]);
    }
    float s = 0.f;
    #pragma unroll
    for (int rr = 0; rr < 8; rr++) s += __expf(Ms[rr] - M) * Ss[rr];
    gLoglik[t] = M + __logf(s);
}

__global__ __launch_bounds__(256) void epilogue_kernel(float* __restrict__ out, int out_size) {
    size_t i4 = (size_t)blockIdx.x * 256 + threadIdx.x;
    float4 o  = ((const float4*)out)[i4];
    float4 bb = ((const float4*)gBeta)[i4];
    float ll = gLoglik[(int)(i4 >> 16)];
    o.x += bb.x - ll; o.y += bb.y - ll; o.z += bb.z - ll; o.w += bb.w - ll;
    ((float4*)out)[i4] = o;
    if (blockIdx.x == 0 && threadIdx.x < NM * NB && out_size >= POST_N + NM * NB)
        out[POST_N + threadIdx.x] = gLoglik[threadIdx.x];
}

extern "C" void kernel_launch(void* const* d_in, const int* in_sizes, int n_in,
                              void* d_out, int out_size) {
    const float* inputs = (const float*)d_in[0];
    const float* tl     = (const float*)d_in[1];
    const float* el     = (const float*)d_in[2];
    const float* il     = (const float*)d_in[3];
    float* out = (float*)d_out;

    cudaFuncSetAttribute(hmm_scan_cluster,
                         cudaFuncAttributeMaxDynamicSharedMemorySize, SMEM_BYTES);

    prep_trans_kernel<<<NM * QQ, 256>>>(tl);
    prep_emis_kernel<<<128, 256>>>(el);
    prep_init_kernel<<<NM, 256>>>(il);
    prep_logE_kernel<<<NM * NB * (LT / 8), 512>>>(inputs);
    hmm_scan_cluster<<<16 * RANKS, 512, SMEM_BYTES>>>(out);
    loglik_kernel<<<1, 64>>>();
    epilogue_kernel<<<POST_N / 4 / 256, 256>>>(out, out_size);
}

// round 17
// speedup vs baseline: 1.5475x; 1.2508x over previous
#include <cuda_runtime.h>
#include <cuda_bf16.h>
#include <cstdint>

#define NM 2
#define NB 32
#define LT 512
#define QQ 512
#define SS 26
#define POST_N (NM*NB*LT*QQ)

#define RANKS 8
#define CCH 8
#define BLK 552                 // 8 chains * 68 (e, padded) + 8 maxes
#define TXB (BLK*4)             // 2208 bytes per copy
#define TXTOT (RANKS*TXB)
#define RBUF (RANKS*BLK)        // 4416 floats per recv buffer

// smem float offsets
#define OFF_A     0             // 512*64 = 32768 floats (128KB)
#define OFF_RECV  32768         // 2*4416 = 8832
#define OFF_STAGE 41600         // 2*552 = 1104
#define OFF_SY    42704         // 128*68 = 8704
#define OFF_WRED  51408         // 16
#define OFF_MLS   51424         // 8
#define OFF_MB    51432         // 2 u64 barriers
#define SMEM_FLOATS 51440
#define SMEM_BYTES (SMEM_FLOATS*4)   // 205760

typedef unsigned long long u64t;

__device__ float gA    [NM * QQ * QQ];
__device__ float gAT   [NM * QQ * QQ];
__device__ float gBT   [NM * SS * QQ];
__device__ float gLinit[NM * QQ];
__device__ float gLogE [NM * NB * LT * QQ];
__device__ float gBeta [NM * NB * LT * QQ];
__device__ float gLoglik[NM * NB];
__device__ float gLLsum [8 * RANKS * CCH];
__device__ float gLLmaxR[8 * RANKS * CCH];

__device__ __forceinline__ uint32_t smem_u32(const void* p) {
    uint32_t a;
    asm("{ .reg .u64 t; cvta.to.shared.u64 t, %1; cvt.u32.u64 %0, t; }" : "=r"(a) : "l"(p));
    return a;
}
__device__ __forceinline__ uint32_t ctarank() {
    uint32_t r; asm("mov.u32 %0, %%cluster_ctarank;" : "=r"(r)); return r;
}
__device__ __forceinline__ void cluster_sync_all() {
    asm volatile("barrier.cluster.arrive.aligned;" ::: "memory");
    asm volatile("barrier.cluster.wait.aligned;" ::: "memory");
}
__device__ __forceinline__ void mbar_wait(uint32_t mbar, uint32_t parity) {
    asm volatile(
        "{\n\t.reg .pred P;\n\t"
        "WL%=:\n\t"
        "mbarrier.try_wait.parity.acquire.cta.shared::cta.b64 P, [%0], %1, 0x989680;\n\t"
        "@P bra.uni WD%=;\n\t"
        "bra.uni WL%=;\n\t"
        "WD%=:\n\t}"
        :: "r"(mbar), "r"(parity) : "memory");
}
__device__ __forceinline__ void mbar_arm(uint32_t mbar, uint32_t tx) {
    asm volatile("mbarrier.arrive.expect_tx.shared.b64 _, [%0], %1;"
                 :: "r"(mbar), "r"(tx) : "memory");
}
__device__ __forceinline__ void fma2(u64t& d, u64t a, u64t b) {
    asm("fma.rn.f32x2 %0, %1, %2, %0;" : "+l"(d) : "l"(a), "l"(b));
}
__device__ __forceinline__ u64t pack2(float x) {
    u64t r; asm("mov.b64 %0, {%1, %1};" : "=l"(r) : "r"(__float_as_uint(x)));
    return r;
}

// --------------------------- prep kernels ----------------------------------
__global__ __launch_bounds__(256) void prep_trans_kernel(const float* __restrict__ tl) {
    __shared__ float red[256];
    int row = blockIdx.x, m = row >> 9, k = row & (QQ - 1), tid = threadIdx.x;
    float x0 = tl[row * QQ + tid], x1 = tl[row * QQ + tid + 256];
    red[tid] = fmaxf(x0, x1); __syncthreads();
    for (int s = 128; s; s >>= 1) { if (tid < s) red[tid] = fmaxf(red[tid], red[tid + s]); __syncthreads(); }
    float M = red[0]; __syncthreads();
    float e0 = __expf(x0 - M), e1 = __expf(x1 - M);
    red[tid] = e0 + e1; __syncthreads();
    for (int s = 128; s; s >>= 1) { if (tid < s) red[tid] += red[tid + s]; __syncthreads(); }
    float inv = 1.f / red[0];
    float p0 = e0 * inv, p1 = e1 * inv;
    gA[row * QQ + tid] = p0; gA[row * QQ + tid + 256] = p1;
    size_t base = (size_t)m * QQ * QQ;
    gAT[base + (size_t)tid * QQ + k] = p0;
    gAT[base + (size_t)(tid + 256) * QQ + k] = p1;
}

__global__ __launch_bounds__(256) void prep_init_kernel(const float* __restrict__ il) {
    __shared__ float red[256];
    int row = blockIdx.x, tid = threadIdx.x;
    float x0 = il[row * QQ + tid], x1 = il[row * QQ + tid + 256];
    red[tid] = fmaxf(x0, x1); __syncthreads();
    for (int s = 128; s; s >>= 1) { if (tid < s) red[tid] = fmaxf(red[tid], red[tid + s]); __syncthreads(); }
    float M = red[0]; __syncthreads();
    float e0 = __expf(x0 - M), e1 = __expf(x1 - M);
    red[tid] = e0 + e1; __syncthreads();
    for (int s = 128; s; s >>= 1) { if (tid < s) red[tid] += red[tid + s]; __syncthreads(); }
    float ls = __logf(red[0]);
    gLinit[row * QQ + tid] = x0 - M - ls;
    gLinit[row * QQ + tid + 256] = x1 - M - ls;
}

__global__ __launch_bounds__(256) void prep_emis_kernel(const float* __restrict__ el) {
    const unsigned full = 0xffffffffu;
    int w = threadIdx.x >> 5, l = threadIdx.x & 31;
    int row = blockIdx.x * 8 + w, m = row >> 9, q = row & (QQ - 1);
    float v = (l < SS) ? el[row * SS + l] : -3.4e38f;
    float M = v;
    #pragma unroll
    for (int o = 16; o; o >>= 1) M = fmaxf(M, __shfl_xor_sync(full, M, o));
    float e = (l < SS) ? __expf(v - M) : 0.f;
    float s = e;
    #pragma unroll
    for (int o = 16; o; o >>= 1) s += __shfl_xor_sync(full, s, o);
    if (l < SS) gBT[(size_t)m * SS * QQ + (size_t)l * QQ + q] = e / s;
}

__global__ __launch_bounds__(512) void prep_logE_kernel(const float* __restrict__ inp) {
    __shared__ float sIn[SS];
    int bx = blockIdx.x, lt = bx & 63, mb = bx >> 6, m = mb >> 5, q = threadIdx.x;
    float breg[SS];
    const float* bt = gBT + (size_t)m * SS * QQ;
    #pragma unroll
    for (int s = 0; s < SS; s++) breg[s] = bt[s * QQ + q];
    const float* ip = inp + ((size_t)mb * LT + (size_t)lt * 8) * SS;
    float* op = gLogE + ((size_t)mb * LT + (size_t)lt * 8) * QQ;
    for (int l = 0; l < 8; l++) {
        __syncthreads();
        if (q < SS) sIn[q] = ip[l * SS + q];
        __syncthreads();
        float em = 0.f;
        #pragma unroll
        for (int s = 0; s < SS; s++) em += breg[s] * sIn[s];
        op[l * QQ + q] = __logf(em + 1e-16f);
    }
}

// ---------------------------------------------------------------------------
// produce: rank-local max shift; e + maxes into stage[sb]; bulk-copy 2208B
// to all 8 ranks' recv[sb], complete_tx on their FULL[sb].
// ---------------------------------------------------------------------------
__device__ __forceinline__ void produce(float g, int sb, int tid, int c, int col,
                                        uint32_t myrank, float* stage, float* recv,
                                        float* wred, float* MlS, uint32_t mb_base) {
    const unsigned full = 0xffffffffu;
    int lane = tid & 31;
    float* stg = stage + sb * BLK;
    float wm = g;
    #pragma unroll
    for (int o = 16; o; o >>= 1) wm = fmaxf(wm, __shfl_xor_sync(full, wm, o));
    if (lane == 0) wred[tid >> 5] = wm;
    __syncthreads();
    if (tid < 8) {
        float lm = fmaxf(wred[2 * tid], wred[2 * tid + 1]);
        MlS[tid] = lm;
        stg[544 + tid] = lm;
    }
    __syncthreads();
    stg[c * 68 + col] = __expf(g - MlS[c]);
    __syncthreads();
    if (tid < 8) {
        asm volatile("fence.proxy.async.shared::cta;" ::: "memory");
        uint32_t src  = smem_u32(stg);
        uint32_t dstl = smem_u32(recv + sb * RBUF + (int)myrank * BLK);
        uint32_t mbl  = mb_base + sb * 8;
        uint32_t peer = (uint32_t)tid;
        uint32_t dstr, mbr;
        asm("mapa.shared::cluster.u32 %0, %1, %2;" : "=r"(dstr) : "r"(dstl), "r"(peer));
        asm("mapa.shared::cluster.u32 %0, %1, %2;" : "=r"(mbr)  : "r"(mbl),  "r"(peer));
        asm volatile(
            "cp.async.bulk.shared::cluster.shared::cta.mbarrier::complete_tx::bytes "
            "[%0], [%1], %2, [%3];"
            :: "r"(dstr), "r"(src), "r"(TXB), "r"(mbr) : "memory");
    }
}

// ---------------------------------------------------------------------------
// Main scan: 16 clusters x 8 CTAs; A resident in SMEM (read 1x per step);
// 256-thread matvec, 8 chains per thread, e warp-broadcast; async exchange.
// ---------------------------------------------------------------------------
__global__ void __launch_bounds__(512, 1) __cluster_dims__(RANKS, 1, 1)
hmm_scan_cluster(float* __restrict__ out) {
    extern __shared__ float sm[];
    float* sA    = sm + OFF_A;
    float* recv  = sm + OFF_RECV;
    float* stage = sm + OFF_STAGE;
    float* sY    = sm + OFF_SY;
    float* wred  = sm + OFF_WRED;
    float* MlS   = sm + OFF_MLS;
    uint32_t mb_base = smem_u32(sm + OFF_MB);

    int tid = threadIdx.x;
    uint32_t r = ctarank();
    int cid = blockIdx.x >> 3;
    int m = cid >> 3, dir = (cid >> 2) & 1, grp = cid & 3;

    const float* Asrc = (dir == 0 ? gA : gAT) + (size_t)m * QQ * QQ + (size_t)r * 64;
    for (int idx = tid; idx < QQ * 16; idx += 512) {
        int k = idx >> 4, c4 = idx & 15;
        ((float4*)sA)[idx] = ((const float4*)(Asrc + (size_t)k * QQ))[c4];
    }

    if (tid == 0) {
        asm volatile("mbarrier.init.shared.b64 [%0], 1;" :: "r"(mb_base));
        asm volatile("mbarrier.init.shared.b64 [%0], 1;" :: "r"(mb_base + 8));
        mbar_arm(mb_base, TXTOT);
        mbar_arm(mb_base + 8, TXTOT);
    }

    int c = tid >> 6, col = tid & 63;            // output mapping
    int kp2 = tid >> 4, cg2 = tid & 15;          // matvec mapping (tid<256)
    int rk = kp2 >> 1, h = kp2 & 1;

    int b = grp * 8 + c;
    const float* le = gLogE + (size_t)(m * NB + b) * LT * QQ;
    float* stp = (dir == 0 ? out : gBeta) + (size_t)(m * NB + b) * LT * QQ;
    int jg = (int)r * 64 + col;

    __syncthreads();
    cluster_sync_all();

    float g;
    if (dir == 0) {
        g = gLinit[m * QQ + jg] + le[jg];
        stp[jg] = g;
    } else {
        stp[(size_t)(LT - 1) * QQ + jg] = 0.f;
        g = le[(size_t)(LT - 1) * QQ + jg];
    }
    produce(g, 1, tid, c, col, r, stage, recv, wred, MlS, mb_base);

    int par[2] = {0, 0};
    for (int i = 1; i < LT; i++) {
        int t = dir ? (LT - 1 - i) : i;
        int bu = i & 1;
        mbar_wait(mb_base + bu * 8, (uint32_t)par[bu]);
        par[bu] ^= 1;
        if (tid == 0) mbar_arm(mb_base + bu * 8, TXTOT);

        float lE = le[(size_t)t * QQ + jg];            // hidden by matvec

        const float* rb = recv + bu * RBUF;

        if (tid < 256) {
            const float* rbb = rb + rk * BLK + h * 32;
            const ulonglong2* Ap = (const ulonglong2*)(sA + kp2 * 32 * 64) + cg2;
            u64t acc[8][2];
            #pragma unroll
            for (int cc = 0; cc < 8; cc++) { acc[cc][0] = 0; acc[cc][1] = 0; }
            #pragma unroll
            for (int j = 0; j < 8; j++) {
                float4 ev[8];
                #pragma unroll
                for (int cc = 0; cc < 8; cc++)
                    ev[cc] = *(const float4*)(rbb + cc * 68 + j * 4);
                #pragma unroll
                for (int kk = 0; kk < 4; kk++) {
                    ulonglong2 au = Ap[(j * 4 + kk) * 16];
                    #pragma unroll
                    for (int cc = 0; cc < 8; cc++) {
                        float es = (kk == 0) ? ev[cc].x : (kk == 1) ? ev[cc].y
                                 : (kk == 2) ? ev[cc].z : ev[cc].w;
                        u64t s = pack2(es);
                        fma2(acc[cc][0], s, au.x);
                        fma2(acc[cc][1], s, au.y);
                    }
                }
            }
            #pragma unroll
            for (int cc = 0; cc < 8; cc++) {
                ulonglong2 t2; t2.x = acc[cc][0]; t2.y = acc[cc][1];
                *(ulonglong2*)(sY + (kp2 * 8 + cc) * 68 + cg2 * 4) = t2;
            }
        }
        __syncthreads();

        // weighted cross-rank reduce: rank rr supplied k-slices kp2 = 2rr, 2rr+1
        float Mv[8];
        #pragma unroll
        for (int rr = 0; rr < 8; rr++) Mv[rr] = rb[rr * BLK + 544 + c];
        float Mgl = Mv[0];
        #pragma unroll
        for (int rr = 1; rr < 8; rr++) Mgl = fmaxf(Mgl, Mv[rr]);
        float y = 0.f;
        #pragma unroll
        for (int rr = 0; rr < 8; rr++) {
            float part = sY[((2 * rr) * 8 + c) * 68 + col]
                       + sY[((2 * rr + 1) * 8 + c) * 68 + col];
            y += __expf(Mv[rr] - Mgl) * part;
        }

        float v, gn;
        if (dir == 0) { v = Mgl + __logf(y) + lE; gn = v; }
        else          { v = Mgl + __logf(y);      gn = v + lE; }
        stp[(size_t)t * QQ + jg] = v;
        g = gn;

        if (i < LT - 1)
            produce(g, (i + 1) & 1, tid, c, col, r, stage, recv, wred, MlS, mb_base);
    }

    if (dir == 0) {
        const unsigned full = 0xffffffffu;
        int lane = tid & 31;
        float wm = g;
        #pragma unroll
        for (int o = 16; o; o >>= 1) wm = fmaxf(wm, __shfl_xor_sync(full, wm, o));
        if (lane == 0) wred[tid >> 5] = wm;
        __syncthreads();
        if (tid < 8) MlS[tid] = fmaxf(wred[2 * tid], wred[2 * tid + 1]);
        __syncthreads();
        float e = __expf(g - MlS[c]);
        float ws = e;
        #pragma unroll
        for (int o = 16; o; o >>= 1) ws += __shfl_xor_sync(full, ws, o);
        if (lane == 0) wred[tid >> 5] = ws;
        __syncthreads();
        if (tid < 8) {
            int team = m * 4 + grp;
            gLLsum [(team * 8 + (int)r) * 8 + tid] = wred[2 * tid] + wred[2 * tid + 1];
            gLLmaxR[(team * 8 + (int)r) * 8 + tid] = MlS[tid];
        }
    }
    cluster_sync_all();
}

__global__ void loglik_kernel() {
    int t = threadIdx.x;
    int mm = t >> 5, bb = t & 31;
    int team = mm * 4 + (bb >> 3), c = bb & 7;
    float Ms[8], Ss[8], M = -3.4e38f;
    #pragma unroll
    for (int rr = 0; rr < 8; rr++) {
        Ms[rr] = gLLmaxR[(team * 8 + rr) * 8 + c];
        Ss[rr] = gLLsum [(team * 8 + rr) * 8 + c];
        M = fmaxf(M, Ms[rr]);
    }
    float s = 0.f;
    #pragma unroll
    for (int rr = 0; rr < 8; rr++) s += __expf(Ms[rr] - M) * Ss[rr];
    gLoglik[t] = M + __logf(s);
}

__global__ __launch_bounds__(256) void epilogue_kernel(float* __restrict__ out, int out_size) {
    size_t i4 = (size_t)blockIdx.x * 256 + threadIdx.x;
    float4 o  = ((const float4*)out)[i4];
    float4 bb = ((const float4*)gBeta)[i4];
    float ll = gLoglik[(int)(i4 >> 16)];
    o.x += bb.x - ll; o.y += bb.y - ll; o.z += bb.z - ll; o.w += bb.w - ll;
    ((float4*)out)[i4] = o;
    if (blockIdx.x == 0 && threadIdx.x < NM * NB && out_size >= POST_N + NM * NB)
        out[POST_N + threadIdx.x] = gLoglik[threadIdx.x];
}

extern "C" void kernel_launch(void* const* d_in, const int* in_sizes, int n_in,
                              void* d_out, int out_size) {
    const float* inputs = (const float*)d_in[0];
    const float* tl     = (const float*)d_in[1];
    const float* el     = (const float*)d_in[2];
    const float* il     = (const float*)d_in[3];
    float* out = (float*)d_out;

    cudaFuncSetAttribute(hmm_scan_cluster,
                         cudaFuncAttributeMaxDynamicSharedMemorySize, SMEM_BYTES);

    prep_trans_kernel<<<NM * QQ, 256>>>(tl);
    prep_emis_kernel<<<128, 256>>>(el);
    prep_init_kernel<<<NM, 256>>>(il);
    prep_logE_kernel<<<NM * NB * (LT / 8), 512>>>(inputs);
    hmm_scan_cluster<<<16 * RANKS, 512, SMEM_BYTES>>>(out);
    loglik_kernel<<<1, 64>>>();
    epilogue_kernel<<<POST_N / 4 / 256, 256>>>(out, out_size);
}